// round 13
// baseline (speedup 1.0000x reference)
#include <cuda_runtime.h>
#include <cuda_bf16.h>
#include <mma.h>
#include <math.h>

using namespace nvcuda;

#define BATCH 4096
#define NTAB  26
#define VOC   100000
#define EDIM  64
#define NPAIR 351
#define RDIM  448          // 64 + 351 padded to mult of 64 (cols 415..447 zeroed)

typedef __nv_bfloat16 bf16;
typedef long long ll;

// ---------------- scratch ----------------
__device__ bf16  g_xp  [BATCH * 64];
__device__ bf16  g_bw0p[512 * 64];
__device__ bf16  g_bw1p[256 * 512];
__device__ bf16  g_bw2p[64 * 256];
__device__ bf16  g_tw0p[512 * RDIM];
__device__ bf16  g_tw1p[256 * 512];
__device__ bf16  g_R   [BATCH * RDIM];

// ---------------- helpers ----------------
__device__ __forceinline__ unsigned su(const void* p) {
    return (unsigned)__cvta_generic_to_shared(p);
}
__device__ __forceinline__ void cpa16(unsigned d, const void* s) {
    asm volatile("cp.async.cg.shared.global [%0], [%1], 16;\n" :: "r"(d), "l"(s));
}

// ---------------- pack: fp32 -> bf16, K padded to mult of 64 ----------------
__global__ void __launch_bounds__(256)
pack_all(const float* x, const float* bw0, const float* bw1, const float* bw2,
         const float* tw0, const float* tw1)
{
    ll gid = (ll)blockIdx.x * 256 + threadIdx.x;
    const float* src; bf16* dst; int K, Kp; ll e;
    if (gid < 262144)       { src = x;   dst = g_xp;   K = 13;  Kp = 64;   e = gid; }
    else if (gid < 294912)  { src = bw0; dst = g_bw0p; K = 13;  Kp = 64;   e = gid - 262144; }
    else if (gid < 425984)  { src = bw1; dst = g_bw1p; K = 512; Kp = 512;  e = gid - 294912; }
    else if (gid < 442368)  { src = bw2; dst = g_bw2p; K = 256; Kp = 256;  e = gid - 425984; }
    else if (gid < 671744)  { src = tw0; dst = g_tw0p; K = 415; Kp = RDIM; e = gid - 442368; }
    else if (gid < 802816)  { src = tw1; dst = g_tw1p; K = 512; Kp = 512;  e = gid - 671744; }
    else return;
    int n = (int)(e / Kp), k = (int)(e % Kp);
    float v = (k < K) ? src[(ll)n * K + k] : 0.f;
    dst[e] = __float2bfloat16_rn(v);
}

// ---------------- fused MLP layer: out = relu(As[32,K] @ W[N,K]^T + bias) ----
// 256 threads / 8 warps; warp = 16x16 tile of the 32x64 output slab.
// W streamed from gmem as 64x64 tiles, cp.async double-buffered.
// Output to smem (ldo) or gmem (ldg, base row bm).
__device__ __forceinline__ void mlp_layer(
    const bf16* As, int lda,
    const bf16* __restrict__ Wg, int kpw,
    const float* __restrict__ bias,
    int ntiles, int nchunks,
    bf16* wbuf, float* csc,
    bf16* outS, int ldo,
    bf16* outG, int ldg, int bm,
    int tid)
{
    const int wid  = tid >> 5;
    const int lane = tid & 31;
    const int warp_m = wid & 1;          // 16-row slab
    const int warp_n = wid >> 1;         // 16-col slab (0..3)
    const int T = ntiles * nchunks;

    auto prefetch = [&](int t) {
        bf16* dst = wbuf + (t & 1) * (64 * 72);
        int nt = t / nchunks, kc = t - nt * nchunks;
        const bf16* src = Wg + (ll)nt * 64 * kpw + kc * 64;
#pragma unroll
        for (int i = 0; i < 2; i++) {
            int id = tid + i * 256;
            int r = id >> 3, c8 = (id & 7) * 8;
            cpa16(su(dst + r * 72 + c8), src + (ll)r * kpw + c8);
        }
        asm volatile("cp.async.commit_group;\n");
    };

    wmma::fragment<wmma::accumulator, 16, 16, 16, float> acc;

    prefetch(0);
    for (int t = 0; t < T; t++) {
        const int nt = t / nchunks, kc = t - nt * nchunks;
        if (t + 1 < T) { prefetch(t + 1); asm volatile("cp.async.wait_group 1;\n"); }
        else           { asm volatile("cp.async.wait_group 0;\n"); }
        __syncthreads();

        if (kc == 0) wmma::fill_fragment(acc, 0.f);
        const bf16* Wt = wbuf + (t & 1) * (64 * 72);
#pragma unroll
        for (int kk = 0; kk < 64; kk += 16) {
            wmma::fragment<wmma::matrix_a, 16, 16, 16, bf16, wmma::row_major> af;
            wmma::fragment<wmma::matrix_b, 16, 16, 16, bf16, wmma::col_major> bfg;
            wmma::load_matrix_sync(af, As + (warp_m * 16) * lda + kc * 64 + kk, lda);
            wmma::load_matrix_sync(bfg, Wt + (warp_n * 16) * 72 + kk, 72);
            wmma::mma_sync(acc, af, bfg, acc);
        }

        if (kc == nchunks - 1) {
            float* Cw = csc + wid * 16 * 20;
            wmma::store_matrix_sync(Cw, acc, 20, wmma::mem_row_major);
            __syncwarp();
            const int cl   = lane & 15;
            const int half = lane >> 4;
            const int colg = nt * 64 + warp_n * 16 + cl;
            const float bv = bias[colg];
#pragma unroll
            for (int i = 0; i < 8; i++) {
                int rl = half * 8 + i;
                float v = fmaxf(Cw[rl * 20 + cl] + bv, 0.f);
                int row = warp_m * 16 + rl;
                if (outS) outS[row * ldo + colg] = __float2bfloat16_rn(v);
                else      outG[(ll)(bm + row) * ldg + colg] = __float2bfloat16_rn(v);
            }
        }
        __syncthreads();
    }
}

// ---------------- fused bottom MLP: x -> h0 -> h1 -> R[:,0:64] ----------------
// smem: A0 [0,4608) | WB [4608,23040) | H0 [23040,56320) | H1 [56320,73216) |
//       CS [73216,83456)
__global__ void __launch_bounds__(256)
fused_bottom(const float* __restrict__ bb0, const float* __restrict__ bb1,
             const float* __restrict__ bb2)
{
    extern __shared__ __align__(16) unsigned char dsm[];
    bf16*  A0 = (bf16*)dsm;                      // 32 x 72
    bf16*  WB = (bf16*)(dsm + 4608);             // 2 x 64 x 72
    bf16*  H0 = (bf16*)(dsm + 23040);            // 32 x 520
    bf16*  H1 = (bf16*)(dsm + 56320);            // 32 x 264
    float* CS = (float*)(dsm + 73216);           // 8 x 16 x 20

    const int tid = threadIdx.x;
    const int bm  = blockIdx.x * 32;

    // load A0: 32 rows x 64 cols = 256 x 16B chunks, 1/thread
    {
        int r = tid >> 3, c8 = (tid & 7) * 8;
        cpa16(su(A0 + r * 72 + c8), g_xp + (ll)(bm + r) * 64 + c8);
        asm volatile("cp.async.commit_group;\ncp.async.wait_group 0;\n");
    }
    __syncthreads();

    mlp_layer(A0, 72,  g_bw0p, 64,  bb0, 8, 1, WB, CS, H0, 520, nullptr, 0, 0, tid);
    mlp_layer(H0, 520, g_bw1p, 512, bb1, 4, 8, WB, CS, H1, 264, nullptr, 0, 0, tid);
    mlp_layer(H1, 264, g_bw2p, 256, bb2, 1, 4, WB, CS, nullptr, 0, g_R, RDIM, bm, tid);
}

// ---------------- fused top MLP: R -> z0 -> z1 -> sigmoid out ----------------
// smem: A0 [0,29184) | WB [29184,47616) | H0 [47616,80896) | H1 [80896,97792) |
//       CS [97792,108032) | WS2 [108032,109056)
__global__ void __launch_bounds__(256)
fused_top(const float* __restrict__ tb0, const float* __restrict__ tb1,
          const float* __restrict__ tw2, const float* __restrict__ tb2,
          float* __restrict__ out)
{
    extern __shared__ __align__(16) unsigned char dsm[];
    bf16*  A0  = (bf16*)dsm;                     // 32 x 456
    bf16*  WB  = (bf16*)(dsm + 29184);
    bf16*  H0  = (bf16*)(dsm + 47616);           // 32 x 520
    bf16*  H1  = (bf16*)(dsm + 80896);           // 32 x 264
    float* CS  = (float*)(dsm + 97792);
    float* WS2 = (float*)(dsm + 108032);         // 256 floats

    const int tid = threadIdx.x;
    const int bm  = blockIdx.x * 32;

    // load A0: 32 rows x 448 cols = 1792 x 16B chunks, 7/thread
#pragma unroll
    for (int i = 0; i < 7; i++) {
        int id = tid + i * 256;
        int r = id / 56, c8 = (id % 56) * 8;
        cpa16(su(A0 + r * 456 + c8), g_R + (ll)(bm + r) * RDIM + c8);
    }
    WS2[tid & 255] = tw2[tid & 255];
    asm volatile("cp.async.commit_group;\ncp.async.wait_group 0;\n");
    __syncthreads();

    mlp_layer(A0, 456, g_tw0p, RDIM, tb0, 8, 7, WB, CS, H0, 520, nullptr, 0, 0, tid);
    mlp_layer(H0, 520, g_tw1p, 512,  tb1, 4, 8, WB, CS, H1, 264, nullptr, 0, 0, tid);

    // gemv + sigmoid: 8 warps x 4 rows
    const int wid = tid >> 5, lane = tid & 31;
    const float b0 = tb2[0];
#pragma unroll
    for (int i = 0; i < 4; i++) {
        int row = wid * 4 + i;
        float4 raw = ((const float4*)(H1 + row * 264))[lane];
        const __nv_bfloat162* pr = (const __nv_bfloat162*)&raw;
        float s = 0.f;
#pragma unroll
        for (int j = 0; j < 4; j++) {
            float2 v = __bfloat1622float2(pr[j]);
            s += v.x * WS2[lane * 8 + 2 * j] + v.y * WS2[lane * 8 + 2 * j + 1];
        }
#pragma unroll
        for (int off = 16; off; off >>= 1) s += __shfl_xor_sync(0xffffffffu, s, off);
        if (lane == 0) out[bm + row] = 1.f / (1.f + expf(-(s + b0)));
    }
}

// ---------------- fused embedding gather + interaction ----------------
__global__ void __launch_bounds__(128)
gather_interact(const void* __restrict__ lsi, const float* __restrict__ emb,
                bf16* __restrict__ R)
{
    __shared__ float Ts[27][68];
    __shared__ int sidx[26][4];
    const int b   = blockIdx.x;
    const int tid = threadIdx.x;

    const unsigned long long* q = (const unsigned long long*)lsi;
    const bool is64 = (q[0] < (unsigned long long)VOC) && (q[1] < (unsigned long long)VOC) &&
                      (q[2] < (unsigned long long)VOC) && (q[3] < (unsigned long long)VOC);

    if (tid < 64) Ts[0][tid] = __bfloat162float(R[(ll)b * RDIM + tid]);
    if (tid < NTAB * 4) {
        int t = tid >> 2, l = tid & 3;
        ll pos = ((ll)t * BATCH + b) * 4 + l;
        sidx[t][l] = is64 ? (int)((const ll*)lsi)[pos] : ((const int*)lsi)[pos];
    }
    __syncthreads();

    for (int u = tid; u < NTAB * 16; u += 128) {
        int t = u >> 4, q4 = u & 15;
        float4 s = make_float4(0.f, 0.f, 0.f, 0.f);
#pragma unroll
        for (int l = 0; l < 4; l++) {
            const float4 v = __ldg((const float4*)(emb +
                ((ll)t * VOC + sidx[t][l]) * EDIM + q4 * 4));
            s.x += v.x; s.y += v.y; s.z += v.z; s.w += v.w;
        }
        *(float4*)&Ts[1 + t][q4 * 4] = s;
    }
    __syncthreads();

    for (int p = tid; p < NPAIR; p += 128) {
        int i = (int)((1.0f + sqrtf(1.0f + 8.0f * (float)p)) * 0.5f);
        while (i * (i - 1) / 2 > p) i--;
        while ((i + 1) * i / 2 <= p) i++;
        int j = p - i * (i - 1) / 2;

        const float4* ri = (const float4*)&Ts[i][0];
        const float4* rj = (const float4*)&Ts[j][0];
        float acc = 0.f;
#pragma unroll
        for (int k = 0; k < EDIM / 4; k++) {
            float4 a = ri[k], c = rj[k];
            acc += a.x * c.x + a.y * c.y + a.z * c.z + a.w * c.w;
        }
        R[(ll)b * RDIM + 64 + p] = __float2bfloat16_rn(acc);
    }
    if (tid < RDIM - 64 - NPAIR)
        R[(ll)b * RDIM + 64 + NPAIR + tid] = __float2bfloat16_rn(0.f);
}

// ---------------- launch ----------------
extern "C" void kernel_launch(void* const* d_in, const int* in_sizes, int n_in,
                              void* d_out, int out_size)
{
    const float* x    = (const float*)d_in[0];
    const void*  lsi  = d_in[1];
    const float* emb  = (const float*)d_in[2];
    const float* bw0  = (const float*)d_in[3];
    const float* bb0  = (const float*)d_in[4];
    const float* bw1  = (const float*)d_in[5];
    const float* bb1  = (const float*)d_in[6];
    const float* bw2  = (const float*)d_in[7];
    const float* bb2  = (const float*)d_in[8];
    const float* tw0  = (const float*)d_in[9];
    const float* tb0  = (const float*)d_in[10];
    const float* tw1  = (const float*)d_in[11];
    const float* tb1  = (const float*)d_in[12];
    const float* tw2  = (const float*)d_in[13];
    const float* tb2  = (const float*)d_in[14];
    float* out = (float*)d_out;

    bf16* R;
    cudaGetSymbolAddress((void**)&R, g_R);

    cudaFuncSetAttribute(fused_bottom, cudaFuncAttributeMaxDynamicSharedMemorySize, 83456);
    cudaFuncSetAttribute(fused_top,    cudaFuncAttributeMaxDynamicSharedMemorySize, 109056);

    pack_all<<<3136, 256>>>(x, bw0, bw1, bw2, tw0, tw1);

    fused_bottom<<<128, 256, 83456>>>(bb0, bb1, bb2);

    gather_interact<<<BATCH, 128>>>(lsi, emb, R);

    fused_top<<<128, 256, 109056>>>(tb0, tb1, tw2, tb2, out);
}